// round 12
// baseline (speedup 1.0000x reference)
#include <cuda_runtime.h>

#define CHANNELS  8
#define IN_CH     8
#define NPARAMS   169      // 80 + 64 + 8 + 8 + 8 + 1
#define H_        128
#define W_        192
#define HW_       (H_ * W_)
#define GI        4        // instances per block in the head kernel
#define MAX_INST  128

// Logits scratch: 128 * 24576 * 4B = 12.6 MB (L2-resident on GB300)
__device__ float g_logits[MAX_INST * HW_];

typedef unsigned long long u64;

// ---- packed fp32x2 helpers (Blackwell) -------------------------------------
__device__ __forceinline__ u64 fma2(u64 a, u64 b, u64 c) {
    u64 d;
    asm("fma.rn.f32x2 %0, %1, %2, %3;" : "=l"(d) : "l"(a), "l"(b), "l"(c));
    return d;
}
__device__ __forceinline__ u64 pack2(float lo, float hi) {
    u64 d;
    asm("mov.b64 %0, {%1, %2};" : "=l"(d) : "f"(lo), "f"(hi));
    return d;
}
__device__ __forceinline__ void unpack2(u64 v, float& lo, float& hi) {
    asm("mov.b64 {%0, %1}, %2;" : "=f"(lo), "=f"(hi) : "l"(v));
}
__device__ __forceinline__ u64 relu2(u64 v) {
    float lo, hi;
    unpack2(v, lo, hi);
    return pack2(fmaxf(lo, 0.0f), fmaxf(hi, 0.0f));
}

// ---------------------------------------------------------------------------
// Kernel 1: dynamic mask head MLP. One thread = 4 consecutive pixels
// (2x f32x2), GI instances per block; weights broadcast from shared memory as
// duplicated float2. fma2 count per unit minimized to 296 (the algorithmic
// minimum): the wy*ry row term is folded once into the bias (byy) instead of
// being applied to each pixel-pair half.
// Measured model: duration = fma2_count / (1 per cyc per SM) — fp32 roofline.
// ---------------------------------------------------------------------------
__global__ __launch_bounds__(256)
void mask_head_kernel(const float* __restrict__ mask_feats,   // (N, 8, H, W)
                      const float* __restrict__ params,       // (n_inst, 169)
                      const float* __restrict__ inst_loc,     // (n_inst, 2)
                      const float* __restrict__ soi_tab,      // (6,)
                      const int*   __restrict__ im_inds,      // (n_inst,)
                      const int*   __restrict__ fpn_levels,   // (n_inst,)
                      int n_inst)
{
    __shared__ float2 sp2[GI * NPARAMS];
    __shared__ float  s_ix[GI], s_iy[GI], s_isoi[GI];
    __shared__ int    s_im[GI];

    const int n0  = blockIdx.y * GI;
    const int tid = threadIdx.x;

    const int g_cnt = min(GI, n_inst - n0);
    for (int i = tid; i < g_cnt * NPARAMS; i += 256) {
        float v = params[(size_t)n0 * NPARAMS + i];
        sp2[i] = make_float2(v, v);
    }
    if (tid < GI && n0 + tid < n_inst) {
        int n = n0 + tid;
        s_ix[tid]   = inst_loc[2 * n + 0];
        s_iy[tid]   = inst_loc[2 * n + 1];
        s_isoi[tid] = 1.0f / soi_tab[fpn_levels[n]];
        s_im[tid]   = im_inds[n];
    }
    __syncthreads();

    const int p0 = (blockIdx.x * 256 + tid) * 4;   // 4 consecutive px, same row
    const int px = p0 % W_;
    const int py = p0 / W_;
    const float lx0 = (float)px * 8.0f + 4.0f;     // MASK_FEAT_STRIDE = 8
    const float ly  = (float)py * 8.0f + 4.0f;

    #pragma unroll 1
    for (int g = 0; g < g_cnt; g++) {
        const u64* prm = reinterpret_cast<const u64*>(sp2) + g * NPARAMS;

        const float s  = s_isoi[g];
        const float dx = s_ix[g] - lx0;
        const float ryv = (s_iy[g] - ly) * s;
        const u64 rx01 = pack2(dx * s,           (dx - 8.0f)  * s);
        const u64 rx23 = pack2((dx - 16.0f) * s, (dx - 24.0f) * s);
        const u64 ry   = pack2(ryv, ryv);

        const float4* f4 = reinterpret_cast<const float4*>(
            mask_feats + (size_t)s_im[g] * IN_CH * HW_ + p0);
        u64 fp01[IN_CH], fp23[IN_CH];
        #pragma unroll
        for (int c = 0; c < IN_CH; c++) {
            float4 v = f4[c * (HW_ / 4)];
            fp01[c] = pack2(v.x, v.y);
            fp23[c] = pack2(v.z, v.w);
        }

        // layer 0: 8 x 10, ReLU.  byy = b + wy*ry computed ONCE per output
        // channel (row term is identical for both pixel-pair halves).
        u64 h01[CHANNELS], h23[CHANNELS];
        #pragma unroll
        for (int o = 0; o < CHANNELS; o++) {
            u64 wx  = prm[o * 10 + 0];
            u64 wy  = prm[o * 10 + 1];
            u64 byy = fma2(wy, ry, prm[152 + o]);
            u64 a0  = fma2(wx, rx01, byy);
            u64 a1  = fma2(wx, rx23, byy);
            #pragma unroll
            for (int c = 0; c < IN_CH; c++) {
                u64 w = prm[o * 10 + 2 + c];
                a0 = fma2(w, fp01[c], a0);
                a1 = fma2(w, fp23[c], a1);
            }
            h01[o] = relu2(a0);
            h23[o] = relu2(a1);
        }

        // layer 1 (ReLU) with layer 2 fused
        u64 acc0 = prm[168], acc1 = prm[168];
        #pragma unroll
        for (int o = 0; o < CHANNELS; o++) {
            u64 b1 = prm[160 + o];
            u64 a0 = b1, a1 = b1;
            #pragma unroll
            for (int c = 0; c < CHANNELS; c++) {
                u64 w = prm[80 + o * 8 + c];
                a0 = fma2(w, h01[c], a0);
                a1 = fma2(w, h23[c], a1);
            }
            u64 w2 = prm[144 + o];
            acc0 = fma2(w2, relu2(a0), acc0);
            acc1 = fma2(w2, relu2(a1), acc1);
        }

        float o0, o1, o2, o3;
        unpack2(acc0, o0, o1);
        unpack2(acc1, o2, o3);
        *reinterpret_cast<float4*>(g_logits + (size_t)(n0 + g) * HW_ + p0) =
            make_float4(o0, o1, o2, o3);
    }
}

// ---------------------------------------------------------------------------
// Kernel 2: aligned 2x bilinear upsample — best measured variant (R9, 11.0us).
// 2 px/thread, zero div/mod mapping: block (96,2), grid (H/2, n_inst).
//   O[2r,  2c  ] = 0.25*(L[r-1,c-1] + L[r-1,c] + L[r,c-1] + L[r,c])
//   O[2r,  2c+1] = 0.5 *(L[r-1,c]   + L[r,c])
//   O[2r+1,2c  ] = 0.5 *(L[r,c-1]   + L[r,c])
//   O[2r+1,2c+1] =       L[r,c]          (r-1, c-1 clamped at 0)
// ---------------------------------------------------------------------------
__global__ __launch_bounds__(192)
void upsample_kernel(float* __restrict__ out)
{
    const int c0 = threadIdx.x * 2;                  // 0..190
    const int r  = blockIdx.x * 2 + threadIdx.y;     // logit row
    const int n  = blockIdx.y;                       // instance

    const float* Ln = g_logits + (size_t)n * HW_;
    const int rm = max(r - 1, 0);
    const int cm = max(c0 - 1, 0);

    // ---- all 4 loads issued before any compute ----
    const float2 t01 = *reinterpret_cast<const float2*>(Ln + rm * W_ + c0);
    const float2 u01 = *reinterpret_cast<const float2*>(Ln + r  * W_ + c0);
    const float  tm  = Ln[rm * W_ + cm];
    const float  um  = Ln[r  * W_ + cm];

    float4 r0, r1;
    r0.x = 0.25f * ((tm + t01.x) + (um + u01.x));
    r0.y = 0.5f  * (t01.x + u01.x);
    r0.z = 0.25f * ((t01.x + t01.y) + (u01.x + u01.y));
    r0.w = 0.5f  * (t01.y + u01.y);
    r1.x = 0.5f  * (um + u01.x);
    r1.y = u01.x;
    r1.z = 0.5f  * (u01.x + u01.y);
    r1.w = u01.y;

    float* o = out + (size_t)n * (4 * HW_) + (size_t)(2 * r) * (2 * W_) + 2 * c0;
    *reinterpret_cast<float4*>(o)          = r0;
    *reinterpret_cast<float4*>(o + 2 * W_) = r1;
}

// ---------------------------------------------------------------------------
extern "C" void kernel_launch(void* const* d_in, const int* in_sizes, int n_in,
                              void* d_out, int out_size)
{
    const float* mask_feats = (const float*)d_in[0];
    const float* params     = (const float*)d_in[1];
    const float* inst_loc   = (const float*)d_in[2];
    const float* soi_tab    = (const float*)d_in[3];
    const int*   im_inds    = (const int*)d_in[4];
    const int*   fpn_levels = (const int*)d_in[5];
    float*       out        = (float*)d_out;

    const int n_inst = in_sizes[1] / NPARAMS;   // 128

    dim3 grid1(HW_ / (256 * 4), (n_inst + GI - 1) / GI);   // 24 x 32
    mask_head_kernel<<<grid1, 256>>>(mask_feats, params, inst_loc, soi_tab,
                                     im_inds, fpn_levels, n_inst);

    dim3 grid2(H_ / 2, n_inst);                            // 64 x 128
    dim3 blk2(96, 2);                                      // 192 threads
    upsample_kernel<<<grid2, blk2>>>(out);
}

// round 13
// speedup vs baseline: 1.0008x; 1.0008x over previous
#include <cuda_runtime.h>

#define CHANNELS  8
#define IN_CH     8
#define NPARAMS   169      // 80 + 64 + 8 + 8 + 8 + 1
#define H_        128
#define W_        192
#define HW_       (H_ * W_)
#define GI        4        // instances per block in the head kernel
#define MAX_INST  128

// Logits scratch: 128 * 24576 * 4B = 12.6 MB (L2-resident on GB300)
__device__ float g_logits[MAX_INST * HW_];

typedef unsigned long long u64;

// ---- packed fp32x2 helpers (Blackwell) -------------------------------------
__device__ __forceinline__ u64 fma2(u64 a, u64 b, u64 c) {
    u64 d;
    asm("fma.rn.f32x2 %0, %1, %2, %3;" : "=l"(d) : "l"(a), "l"(b), "l"(c));
    return d;
}
__device__ __forceinline__ u64 pack2(float lo, float hi) {
    u64 d;
    asm("mov.b64 %0, {%1, %2};" : "=l"(d) : "f"(lo), "f"(hi));
    return d;
}
__device__ __forceinline__ void unpack2(u64 v, float& lo, float& hi) {
    asm("mov.b64 {%0, %1}, %2;" : "=f"(lo), "=f"(hi) : "l"(v));
}
__device__ __forceinline__ u64 relu2(u64 v) {
    float lo, hi;
    unpack2(v, lo, hi);
    return pack2(fmaxf(lo, 0.0f), fmaxf(hi, 0.0f));
}

// ---------------------------------------------------------------------------
// Kernel 1: dynamic mask head MLP. One thread = 4 consecutive pixels
// (2x f32x2), GI instances per block; weights broadcast from shared memory as
// duplicated float2. 296 fma2/unit = algorithmic minimum (wy*ry folded once
// into the bias). Measured at 97% of the fp32 FFMA roofline — converged.
// ---------------------------------------------------------------------------
__global__ __launch_bounds__(256)
void mask_head_kernel(const float* __restrict__ mask_feats,   // (N, 8, H, W)
                      const float* __restrict__ params,       // (n_inst, 169)
                      const float* __restrict__ inst_loc,     // (n_inst, 2)
                      const float* __restrict__ soi_tab,      // (6,)
                      const int*   __restrict__ im_inds,      // (n_inst,)
                      const int*   __restrict__ fpn_levels,   // (n_inst,)
                      int n_inst)
{
    __shared__ float2 sp2[GI * NPARAMS];
    __shared__ float  s_ix[GI], s_iy[GI], s_isoi[GI];
    __shared__ int    s_im[GI];

    const int n0  = blockIdx.y * GI;
    const int tid = threadIdx.x;

    const int g_cnt = min(GI, n_inst - n0);
    for (int i = tid; i < g_cnt * NPARAMS; i += 256) {
        float v = params[(size_t)n0 * NPARAMS + i];
        sp2[i] = make_float2(v, v);
    }
    if (tid < GI && n0 + tid < n_inst) {
        int n = n0 + tid;
        s_ix[tid]   = inst_loc[2 * n + 0];
        s_iy[tid]   = inst_loc[2 * n + 1];
        s_isoi[tid] = 1.0f / soi_tab[fpn_levels[n]];
        s_im[tid]   = im_inds[n];
    }
    __syncthreads();

    const int p0 = (blockIdx.x * 256 + tid) * 4;   // 4 consecutive px, same row
    const int px = p0 % W_;
    const int py = p0 / W_;
    const float lx0 = (float)px * 8.0f + 4.0f;     // MASK_FEAT_STRIDE = 8
    const float ly  = (float)py * 8.0f + 4.0f;

    #pragma unroll 1
    for (int g = 0; g < g_cnt; g++) {
        const u64* prm = reinterpret_cast<const u64*>(sp2) + g * NPARAMS;

        const float s  = s_isoi[g];
        const float dx = s_ix[g] - lx0;
        const float ryv = (s_iy[g] - ly) * s;
        const u64 rx01 = pack2(dx * s,           (dx - 8.0f)  * s);
        const u64 rx23 = pack2((dx - 16.0f) * s, (dx - 24.0f) * s);
        const u64 ry   = pack2(ryv, ryv);

        const float4* f4 = reinterpret_cast<const float4*>(
            mask_feats + (size_t)s_im[g] * IN_CH * HW_ + p0);
        u64 fp01[IN_CH], fp23[IN_CH];
        #pragma unroll
        for (int c = 0; c < IN_CH; c++) {
            float4 v = f4[c * (HW_ / 4)];
            fp01[c] = pack2(v.x, v.y);
            fp23[c] = pack2(v.z, v.w);
        }

        // layer 0: 8 x 10, ReLU.  byy = b + wy*ry once per output channel.
        u64 h01[CHANNELS], h23[CHANNELS];
        #pragma unroll
        for (int o = 0; o < CHANNELS; o++) {
            u64 wx  = prm[o * 10 + 0];
            u64 wy  = prm[o * 10 + 1];
            u64 byy = fma2(wy, ry, prm[152 + o]);
            u64 a0  = fma2(wx, rx01, byy);
            u64 a1  = fma2(wx, rx23, byy);
            #pragma unroll
            for (int c = 0; c < IN_CH; c++) {
                u64 w = prm[o * 10 + 2 + c];
                a0 = fma2(w, fp01[c], a0);
                a1 = fma2(w, fp23[c], a1);
            }
            h01[o] = relu2(a0);
            h23[o] = relu2(a1);
        }

        // layer 1 (ReLU) with layer 2 fused
        u64 acc0 = prm[168], acc1 = prm[168];
        #pragma unroll
        for (int o = 0; o < CHANNELS; o++) {
            u64 b1 = prm[160 + o];
            u64 a0 = b1, a1 = b1;
            #pragma unroll
            for (int c = 0; c < CHANNELS; c++) {
                u64 w = prm[80 + o * 8 + c];
                a0 = fma2(w, h01[c], a0);
                a1 = fma2(w, h23[c], a1);
            }
            u64 w2 = prm[144 + o];
            acc0 = fma2(w2, relu2(a0), acc0);
            acc1 = fma2(w2, relu2(a1), acc1);
        }

        float o0, o1, o2, o3;
        unpack2(acc0, o0, o1);
        unpack2(acc1, o2, o3);
        *reinterpret_cast<float4*>(g_logits + (size_t)(n0 + g) * HW_ + p0) =
            make_float4(o0, o1, o2, o3);
    }
}

// ---------------------------------------------------------------------------
// Kernel 2: aligned 2x bilinear upsample, smem-staged.
// One block = (instance, 4 logit rows). Stage the 5 needed logit rows
// (1 halo above, clamped) into shared memory with fully-coalesced float4
// LDGs (no duplicate row reads), then compute from smem and store 4x STG.128
// per thread. Gmem logit read traffic drops 2.6x vs the per-thread variant.
//   O[2r,  2c  ] = 0.25*(L[r-1,c-1] + L[r-1,c] + L[r,c-1] + L[r,c])
//   O[2r,  2c+1] = 0.5 *(L[r-1,c]   + L[r,c])
//   O[2r+1,2c  ] = 0.5 *(L[r,c-1]   + L[r,c])
//   O[2r+1,2c+1] =       L[r,c]          (r-1, c-1 clamped at 0)
// Block (96,2), grid (H/4, n_inst).
// ---------------------------------------------------------------------------
__global__ __launch_bounds__(192)
void upsample_kernel(float* __restrict__ out)
{
    __shared__ __align__(16) float srow[5][W_];   // rows r0-1 .. r0+3

    const int n  = blockIdx.y;                    // instance
    const int r0 = blockIdx.x * 4;                // first logit row of block
    const int tid = threadIdx.x + threadIdx.y * 96;

    const float* Ln = g_logits + (size_t)n * HW_;

    // ---- stage 5 rows, coalesced float4 (240 float4, 192 threads) ----------
    #pragma unroll
    for (int i = tid; i < 5 * (W_ / 4); i += 192) {
        const int rr = i / (W_ / 4);              // 0..4
        const int cc = (i % (W_ / 4)) * 4;
        const int gr = max(r0 - 1 + rr, 0);       // halo clamp (top only; r0+3 <= 127)
        *reinterpret_cast<float4*>(&srow[rr][cc]) =
            *reinterpret_cast<const float4*>(Ln + (size_t)gr * W_ + cc);
    }
    __syncthreads();

    // ---- compute: each thread 2 row-units x 2 cols --------------------------
    const int c0 = threadIdx.x * 2;               // 0..190
    const int cm = max(c0 - 1, 0);

    #pragma unroll
    for (int k = 0; k < 2; k++) {
        const int lr = threadIdx.y * 2 + k;       // 0..3
        const float* top = srow[lr];              // L[r-1]  (srow[0] = row r0-1)
        const float* bot = srow[lr + 1];          // L[r]

        const float2 t01 = *reinterpret_cast<const float2*>(&top[c0]);
        const float2 u01 = *reinterpret_cast<const float2*>(&bot[c0]);
        const float  tm  = top[cm];
        const float  um  = bot[cm];

        float4 q0, q1;
        q0.x = 0.25f * ((tm + t01.x) + (um + u01.x));
        q0.y = 0.5f  * (t01.x + u01.x);
        q0.z = 0.25f * ((t01.x + t01.y) + (u01.x + u01.y));
        q0.w = 0.5f  * (t01.y + u01.y);
        q1.x = 0.5f  * (um + u01.x);
        q1.y = u01.x;
        q1.z = 0.5f  * (u01.x + u01.y);
        q1.w = u01.y;

        const int r = r0 + lr;                    // global logit row
        float* o = out + (size_t)n * (4 * HW_)
                       + (size_t)(2 * r) * (2 * W_) + 2 * c0;
        *reinterpret_cast<float4*>(o)          = q0;
        *reinterpret_cast<float4*>(o + 2 * W_) = q1;
    }
}

// ---------------------------------------------------------------------------
extern "C" void kernel_launch(void* const* d_in, const int* in_sizes, int n_in,
                              void* d_out, int out_size)
{
    const float* mask_feats = (const float*)d_in[0];
    const float* params     = (const float*)d_in[1];
    const float* inst_loc   = (const float*)d_in[2];
    const float* soi_tab    = (const float*)d_in[3];
    const int*   im_inds    = (const int*)d_in[4];
    const int*   fpn_levels = (const int*)d_in[5];
    float*       out        = (float*)d_out;

    const int n_inst = in_sizes[1] / NPARAMS;   // 128

    dim3 grid1(HW_ / (256 * 4), (n_inst + GI - 1) / GI);   // 24 x 32
    mask_head_kernel<<<grid1, 256>>>(mask_feats, params, inst_loc, soi_tab,
                                     im_inds, fpn_levels, n_inst);

    dim3 grid2(H_ / 4, n_inst);                            // 32 x 128
    dim3 blk2(96, 2);                                      // 192 threads
    upsample_kernel<<<grid2, blk2>>>(out);
}

// round 14
// speedup vs baseline: 1.0437x; 1.0428x over previous
#include <cuda_runtime.h>

#define CHANNELS  8
#define IN_CH     8
#define NPARAMS   169      // 80 + 64 + 8 + 8 + 8 + 1
#define H_        128
#define W_        192
#define HW_       (H_ * W_)
#define GI        4        // instances per block in the head kernel
#define MAX_INST  128

// Boundary logits (only rows r%4==0 and r%4==3 are written/needed)
__device__ float g_logits[MAX_INST * HW_];

typedef unsigned long long u64;

// ---- packed fp32x2 helpers (Blackwell) -------------------------------------
__device__ __forceinline__ u64 fma2(u64 a, u64 b, u64 c) {
    u64 d;
    asm("fma.rn.f32x2 %0, %1, %2, %3;" : "=l"(d) : "l"(a), "l"(b), "l"(c));
    return d;
}
__device__ __forceinline__ u64 pack2(float lo, float hi) {
    u64 d;
    asm("mov.b64 %0, {%1, %2};" : "=l"(d) : "f"(lo), "f"(hi));
    return d;
}
__device__ __forceinline__ void unpack2(u64 v, float& lo, float& hi) {
    asm("mov.b64 {%0, %1}, %2;" : "=f"(lo), "=f"(hi) : "l"(v));
}
__device__ __forceinline__ u64 relu2(u64 v) {
    float lo, hi;
    unpack2(v, lo, hi);
    return pack2(fmaxf(lo, 0.0f), fmaxf(hi, 0.0f));
}

// ---------------------------------------------------------------------------
// Kernel 1: MLP + 7/8 of the aligned-2x upsample.
// Block = 4 logit rows x 48 col-strips (192 threads), GI instances.
// Per instance g:
//   1. each thread computes logits o0..o3 for (row r, cols c0..c0+3)
//      with the proven 296-fma2 body (fp32 roofline).
//   2. stage to smem; write g_logits only for lr in {0,3} (k2 boundary rows).
//   3. write output: odd rows 2r+1 (all lr) and even rows 2r (lr>=1, top row
//      is in-block). Even rows at r%4==0 are left for kernel 2.
// Upsample identities (r-1, c-1 clamped at 0):
//   O[2r,  2c  ] = 0.25*(L[r-1,c-1] + L[r-1,c] + L[r,c-1] + L[r,c])
//   O[2r,  2c+1] = 0.5 *(L[r-1,c]   + L[r,c])
//   O[2r+1,2c  ] = 0.5 *(L[r,c-1]   + L[r,c])
//   O[2r+1,2c+1] =       L[r,c]
// ---------------------------------------------------------------------------
__global__ __launch_bounds__(192)
void mask_head_kernel(const float* __restrict__ mask_feats,   // (N, 8, H, W)
                      const float* __restrict__ params,       // (n_inst, 169)
                      const float* __restrict__ inst_loc,     // (n_inst, 2)
                      const float* __restrict__ soi_tab,      // (6,)
                      const int*   __restrict__ im_inds,      // (n_inst,)
                      const int*   __restrict__ fpn_levels,   // (n_inst,)
                      float*       __restrict__ out,
                      int n_inst)
{
    __shared__ float2 sp2[GI * NPARAMS];           // duplicated weights
    __shared__ __align__(16) float st[4][W_];      // 4-row logit stage
    __shared__ float  s_ix[GI], s_iy[GI], s_isoi[GI];
    __shared__ int    s_im[GI];

    const int tid = threadIdx.x;
    const int lr  = tid / 48;                      // row within block (0..3)
    const int lc  = tid % 48;
    const int c0  = lc * 4;                        // first col of strip
    const int r   = blockIdx.x * 4 + lr;           // global logit row
    const int n0  = blockIdx.y * GI;

    const int g_cnt = min(GI, n_inst - n0);
    for (int i = tid; i < g_cnt * NPARAMS; i += 192) {
        float v = params[(size_t)n0 * NPARAMS + i];
        sp2[i] = make_float2(v, v);
    }
    if (tid < GI && n0 + tid < n_inst) {
        int n = n0 + tid;
        s_ix[tid]   = inst_loc[2 * n + 0];
        s_iy[tid]   = inst_loc[2 * n + 1];
        s_isoi[tid] = 1.0f / soi_tab[fpn_levels[n]];
        s_im[tid]   = im_inds[n];
    }
    __syncthreads();

    const int p0 = r * W_ + c0;
    const float lx0 = (float)c0 * 8.0f + 4.0f;     // MASK_FEAT_STRIDE = 8
    const float ly  = (float)r  * 8.0f + 4.0f;

    #pragma unroll 1
    for (int g = 0; g < g_cnt; g++) {
        const u64* prm = reinterpret_cast<const u64*>(sp2) + g * NPARAMS;

        const float s  = s_isoi[g];
        const float dx = s_ix[g] - lx0;
        const float ryv = (s_iy[g] - ly) * s;
        const u64 rx01 = pack2(dx * s,           (dx - 8.0f)  * s);
        const u64 rx23 = pack2((dx - 16.0f) * s, (dx - 24.0f) * s);
        const u64 ry   = pack2(ryv, ryv);

        const float4* f4 = reinterpret_cast<const float4*>(
            mask_feats + (size_t)s_im[g] * IN_CH * HW_ + p0);
        u64 fp01[IN_CH], fp23[IN_CH];
        #pragma unroll
        for (int c = 0; c < IN_CH; c++) {
            float4 v = f4[c * (HW_ / 4)];
            fp01[c] = pack2(v.x, v.y);
            fp23[c] = pack2(v.z, v.w);
        }

        // layer 0: 8 x 10, ReLU (byy = b + wy*ry once per output channel)
        u64 h01[CHANNELS], h23[CHANNELS];
        #pragma unroll
        for (int o = 0; o < CHANNELS; o++) {
            u64 wx  = prm[o * 10 + 0];
            u64 wy  = prm[o * 10 + 1];
            u64 byy = fma2(wy, ry, prm[152 + o]);
            u64 a0  = fma2(wx, rx01, byy);
            u64 a1  = fma2(wx, rx23, byy);
            #pragma unroll
            for (int c = 0; c < IN_CH; c++) {
                u64 w = prm[o * 10 + 2 + c];
                a0 = fma2(w, fp01[c], a0);
                a1 = fma2(w, fp23[c], a1);
            }
            h01[o] = relu2(a0);
            h23[o] = relu2(a1);
        }

        // layer 1 (ReLU) with layer 2 fused
        u64 acc0 = prm[168], acc1 = prm[168];
        #pragma unroll
        for (int o = 0; o < CHANNELS; o++) {
            u64 b1 = prm[160 + o];
            u64 a0 = b1, a1 = b1;
            #pragma unroll
            for (int c = 0; c < CHANNELS; c++) {
                u64 w = prm[80 + o * 8 + c];
                a0 = fma2(w, h01[c], a0);
                a1 = fma2(w, h23[c], a1);
            }
            u64 w2 = prm[144 + o];
            acc0 = fma2(w2, relu2(a0), acc0);
            acc1 = fma2(w2, relu2(a1), acc1);
        }

        float o0, o1, o2, o3;
        unpack2(acc0, o0, o1);
        unpack2(acc1, o2, o3);

        // stage logits; gmem boundary rows for kernel 2
        *reinterpret_cast<float4*>(&st[lr][c0]) = make_float4(o0, o1, o2, o3);
        if (lr == 0 || lr == 3)
            *reinterpret_cast<float4*>(
                g_logits + (size_t)(n0 + g) * HW_ + p0) =
                make_float4(o0, o1, o2, o3);
        __syncthreads();

        float* obase = out + (size_t)(n0 + g) * (4 * HW_) + 2 * c0;
        const float left = st[lr][(c0 == 0) ? 0 : c0 - 1];

        // ---- odd output row 2r+1 (needs only row r) ----
        {
            float4 qa = make_float4(0.5f * (left + o0), o0,
                                    0.5f * (o0 + o1),   o1);
            float4 qb = make_float4(0.5f * (o1 + o2),   o2,
                                    0.5f * (o2 + o3),   o3);
            float* orow = obase + (size_t)(2 * r + 1) * (2 * W_);
            reinterpret_cast<float4*>(orow)[0] = qa;
            reinterpret_cast<float4*>(orow)[1] = qb;
        }

        // ---- even output row 2r (needs row r-1: in-block for lr>=1) ----
        if (lr >= 1) {
            const float4 top  = *reinterpret_cast<const float4*>(&st[lr - 1][c0]);
            const float  topL = st[lr - 1][(c0 == 0) ? 0 : c0 - 1];

            const float sL = topL  + left;
            const float s0 = top.x + o0;
            const float s1 = top.y + o1;
            const float s2 = top.z + o2;
            const float s3 = top.w + o3;

            float4 qa = make_float4(0.25f * (sL + s0), 0.5f * s0,
                                    0.25f * (s0 + s1), 0.5f * s1);
            float4 qb = make_float4(0.25f * (s1 + s2), 0.5f * s2,
                                    0.25f * (s2 + s3), 0.5f * s3);
            float* orow = obase + (size_t)(2 * r) * (2 * W_);
            reinterpret_cast<float4*>(orow)[0] = qa;
            reinterpret_cast<float4*>(orow)[1] = qb;
        }
        __syncthreads();   // stage reused next g
    }
}

// ---------------------------------------------------------------------------
// Kernel 2 (lite): even output rows at logit rows r = 4k (1/8 of the output).
// Reads boundary logit rows 4k-1 (clamped for k=0) and 4k from g_logits.
// Block 96 threads (2 cols each), grid (H/4, n_inst).
// ---------------------------------------------------------------------------
__global__ __launch_bounds__(96)
void upsample_boundary_kernel(float* __restrict__ out)
{
    const int c0 = threadIdx.x * 2;              // 0..190
    const int r  = blockIdx.x * 4;               // logit row (r % 4 == 0)
    const int n  = blockIdx.y;                   // instance

    const float* Ln = g_logits + (size_t)n * HW_;
    const int rm = max(r - 1, 0);
    const int cm = max(c0 - 1, 0);

    const float2 t01 = *reinterpret_cast<const float2*>(Ln + rm * W_ + c0);
    const float2 u01 = *reinterpret_cast<const float2*>(Ln + r  * W_ + c0);
    const float  tm  = Ln[rm * W_ + cm];
    const float  um  = Ln[r  * W_ + cm];

    float4 q;
    q.x = 0.25f * ((tm + t01.x) + (um + u01.x));
    q.y = 0.5f  * (t01.x + u01.x);
    q.z = 0.25f * ((t01.x + t01.y) + (u01.x + u01.y));
    q.w = 0.5f  * (t01.y + u01.y);

    float* o = out + (size_t)n * (4 * HW_) + (size_t)(2 * r) * (2 * W_) + 2 * c0;
    *reinterpret_cast<float4*>(o) = q;
}

// ---------------------------------------------------------------------------
extern "C" void kernel_launch(void* const* d_in, const int* in_sizes, int n_in,
                              void* d_out, int out_size)
{
    const float* mask_feats = (const float*)d_in[0];
    const float* params     = (const float*)d_in[1];
    const float* inst_loc   = (const float*)d_in[2];
    const float* soi_tab    = (const float*)d_in[3];
    const int*   im_inds    = (const int*)d_in[4];
    const int*   fpn_levels = (const int*)d_in[5];
    float*       out        = (float*)d_out;

    const int n_inst = in_sizes[1] / NPARAMS;   // 128

    dim3 grid1(H_ / 4, (n_inst + GI - 1) / GI);       // 32 x 32 = 1024 blocks
    mask_head_kernel<<<grid1, 192>>>(mask_feats, params, inst_loc, soi_tab,
                                     im_inds, fpn_levels, out, n_inst);

    dim3 grid2(H_ / 4, n_inst);                       // 32 x 128
    upsample_boundary_kernel<<<grid2, 96>>>(out);
}

// round 15
// speedup vs baseline: 1.0555x; 1.0113x over previous
#include <cuda_runtime.h>

#define CHANNELS  8
#define IN_CH     8
#define NPARAMS   169      // 80 + 64 + 8 + 8 + 8 + 1
#define H_        128
#define W_        192
#define HW_       (H_ * W_)
#define GI        4        // instances per block in the head kernel
#define MAX_INST  128

// Boundary logits (only rows r%4==0 and r%4==3 are written/needed)
__device__ float g_logits[MAX_INST * HW_];

typedef unsigned long long u64;

// ---- packed fp32x2 helpers (Blackwell) -------------------------------------
__device__ __forceinline__ u64 fma2(u64 a, u64 b, u64 c) {
    u64 d;
    asm("fma.rn.f32x2 %0, %1, %2, %3;" : "=l"(d) : "l"(a), "l"(b), "l"(c));
    return d;
}
__device__ __forceinline__ u64 pack2(float lo, float hi) {
    u64 d;
    asm("mov.b64 %0, {%1, %2};" : "=l"(d) : "f"(lo), "f"(hi));
    return d;
}
__device__ __forceinline__ void unpack2(u64 v, float& lo, float& hi) {
    asm("mov.b64 {%0, %1}, %2;" : "=f"(lo), "=f"(hi) : "l"(v));
}
__device__ __forceinline__ u64 relu2(u64 v) {
    float lo, hi;
    unpack2(v, lo, hi);
    return pack2(fmaxf(lo, 0.0f), fmaxf(hi, 0.0f));
}

// ---------------------------------------------------------------------------
// Kernel 1: MLP + 7/8 of the aligned-2x upsample (R14, best measured).
// Block = 4 logit rows x 48 col-strips (192 threads), GI instances.
// Per instance g:
//   1. each thread computes logits o0..o3 for (row r, cols c0..c0+3)
//      with the proven 296-fma2 body (fp32 roofline).
//   2. stage to smem; write g_logits only for lr in {0,3} (k2 boundary rows).
//   3. write output: odd rows 2r+1 (all lr) and even rows 2r (lr>=1, top row
//      is in-block). Even rows at r%4==0 are left for kernel 2.
// Upsample identities (r-1, c-1 clamped at 0):
//   O[2r,  2c  ] = 0.25*(L[r-1,c-1] + L[r-1,c] + L[r,c-1] + L[r,c])
//   O[2r,  2c+1] = 0.5 *(L[r-1,c]   + L[r,c])
//   O[2r+1,2c  ] = 0.5 *(L[r,c-1]   + L[r,c])
//   O[2r+1,2c+1] =       L[r,c]
// ---------------------------------------------------------------------------
__global__ __launch_bounds__(192)
void mask_head_kernel(const float* __restrict__ mask_feats,   // (N, 8, H, W)
                      const float* __restrict__ params,       // (n_inst, 169)
                      const float* __restrict__ inst_loc,     // (n_inst, 2)
                      const float* __restrict__ soi_tab,      // (6,)
                      const int*   __restrict__ im_inds,      // (n_inst,)
                      const int*   __restrict__ fpn_levels,   // (n_inst,)
                      float*       __restrict__ out,
                      int n_inst)
{
    __shared__ float2 sp2[GI * NPARAMS];           // duplicated weights
    __shared__ __align__(16) float st[4][W_];      // 4-row logit stage
    __shared__ float  s_ix[GI], s_iy[GI], s_isoi[GI];
    __shared__ int    s_im[GI];

    const int tid = threadIdx.x;
    const int lr  = tid / 48;                      // row within block (0..3)
    const int lc  = tid % 48;
    const int c0  = lc * 4;                        // first col of strip
    const int r   = blockIdx.x * 4 + lr;           // global logit row
    const int n0  = blockIdx.y * GI;

    const int g_cnt = min(GI, n_inst - n0);
    for (int i = tid; i < g_cnt * NPARAMS; i += 192) {
        float v = params[(size_t)n0 * NPARAMS + i];
        sp2[i] = make_float2(v, v);
    }
    if (tid < GI && n0 + tid < n_inst) {
        int n = n0 + tid;
        s_ix[tid]   = inst_loc[2 * n + 0];
        s_iy[tid]   = inst_loc[2 * n + 1];
        s_isoi[tid] = 1.0f / soi_tab[fpn_levels[n]];
        s_im[tid]   = im_inds[n];
    }
    __syncthreads();

    const int p0 = r * W_ + c0;
    const float lx0 = (float)c0 * 8.0f + 4.0f;     // MASK_FEAT_STRIDE = 8
    const float ly  = (float)r  * 8.0f + 4.0f;

    #pragma unroll 1
    for (int g = 0; g < g_cnt; g++) {
        const u64* prm = reinterpret_cast<const u64*>(sp2) + g * NPARAMS;

        const float s  = s_isoi[g];
        const float dx = s_ix[g] - lx0;
        const float ryv = (s_iy[g] - ly) * s;
        const u64 rx01 = pack2(dx * s,           (dx - 8.0f)  * s);
        const u64 rx23 = pack2((dx - 16.0f) * s, (dx - 24.0f) * s);
        const u64 ry   = pack2(ryv, ryv);

        const float4* f4 = reinterpret_cast<const float4*>(
            mask_feats + (size_t)s_im[g] * IN_CH * HW_ + p0);
        u64 fp01[IN_CH], fp23[IN_CH];
        #pragma unroll
        for (int c = 0; c < IN_CH; c++) {
            float4 v = f4[c * (HW_ / 4)];
            fp01[c] = pack2(v.x, v.y);
            fp23[c] = pack2(v.z, v.w);
        }

        // layer 0: 8 x 10, ReLU (byy = b + wy*ry once per output channel)
        u64 h01[CHANNELS], h23[CHANNELS];
        #pragma unroll
        for (int o = 0; o < CHANNELS; o++) {
            u64 wx  = prm[o * 10 + 0];
            u64 wy  = prm[o * 10 + 1];
            u64 byy = fma2(wy, ry, prm[152 + o]);
            u64 a0  = fma2(wx, rx01, byy);
            u64 a1  = fma2(wx, rx23, byy);
            #pragma unroll
            for (int c = 0; c < IN_CH; c++) {
                u64 w = prm[o * 10 + 2 + c];
                a0 = fma2(w, fp01[c], a0);
                a1 = fma2(w, fp23[c], a1);
            }
            h01[o] = relu2(a0);
            h23[o] = relu2(a1);
        }

        // layer 1 (ReLU) with layer 2 fused
        u64 acc0 = prm[168], acc1 = prm[168];
        #pragma unroll
        for (int o = 0; o < CHANNELS; o++) {
            u64 b1 = prm[160 + o];
            u64 a0 = b1, a1 = b1;
            #pragma unroll
            for (int c = 0; c < CHANNELS; c++) {
                u64 w = prm[80 + o * 8 + c];
                a0 = fma2(w, h01[c], a0);
                a1 = fma2(w, h23[c], a1);
            }
            u64 w2 = prm[144 + o];
            acc0 = fma2(w2, relu2(a0), acc0);
            acc1 = fma2(w2, relu2(a1), acc1);
        }

        float o0, o1, o2, o3;
        unpack2(acc0, o0, o1);
        unpack2(acc1, o2, o3);

        // stage logits; gmem boundary rows for kernel 2
        *reinterpret_cast<float4*>(&st[lr][c0]) = make_float4(o0, o1, o2, o3);
        if (lr == 0 || lr == 3)
            *reinterpret_cast<float4*>(
                g_logits + (size_t)(n0 + g) * HW_ + p0) =
                make_float4(o0, o1, o2, o3);
        __syncthreads();

        float* obase = out + (size_t)(n0 + g) * (4 * HW_) + 2 * c0;
        const float left = st[lr][(c0 == 0) ? 0 : c0 - 1];

        // ---- odd output row 2r+1 (needs only row r) ----
        {
            float4 qa = make_float4(0.5f * (left + o0), o0,
                                    0.5f * (o0 + o1),   o1);
            float4 qb = make_float4(0.5f * (o1 + o2),   o2,
                                    0.5f * (o2 + o3),   o3);
            float* orow = obase + (size_t)(2 * r + 1) * (2 * W_);
            reinterpret_cast<float4*>(orow)[0] = qa;
            reinterpret_cast<float4*>(orow)[1] = qb;
        }

        // ---- even output row 2r (needs row r-1: in-block for lr>=1) ----
        if (lr >= 1) {
            const float4 top  = *reinterpret_cast<const float4*>(&st[lr - 1][c0]);
            const float  topL = st[lr - 1][(c0 == 0) ? 0 : c0 - 1];

            const float sL = topL  + left;
            const float s0 = top.x + o0;
            const float s1 = top.y + o1;
            const float s2 = top.z + o2;
            const float s3 = top.w + o3;

            float4 qa = make_float4(0.25f * (sL + s0), 0.5f * s0,
                                    0.25f * (s0 + s1), 0.5f * s1);
            float4 qb = make_float4(0.25f * (s1 + s2), 0.5f * s2,
                                    0.25f * (s2 + s3), 0.5f * s3);
            float* orow = obase + (size_t)(2 * r) * (2 * W_);
            reinterpret_cast<float4*>(orow)[0] = qa;
            reinterpret_cast<float4*>(orow)[1] = qb;
        }
        __syncthreads();   // stage reused next g
    }
}

// ---------------------------------------------------------------------------
// Kernel 2 (lite): even output rows at logit rows r = 4k (1/8 of the output).
// Reads boundary logit rows 4k-1 (clamped for k=0) and 4k from g_logits.
// Reshaped: block (96,4) = 384 threads covering 4 boundary rows of one
// instance; grid (8, n_inst) = 1024 blocks. Same per-thread work shape as the
// measured-best variant, 4x fatter blocks for latency hiding.
// ---------------------------------------------------------------------------
__global__ __launch_bounds__(384)
void upsample_boundary_kernel(float* __restrict__ out)
{
    const int c0 = threadIdx.x * 2;                          // 0..190
    const int r  = (blockIdx.x * 4 + threadIdx.y) * 4;       // logit row, %4==0
    const int n  = blockIdx.y;                               // instance

    const float* Ln = g_logits + (size_t)n * HW_;
    const int rm = max(r - 1, 0);
    const int cm = max(c0 - 1, 0);

    const float2 t01 = *reinterpret_cast<const float2*>(Ln + rm * W_ + c0);
    const float2 u01 = *reinterpret_cast<const float2*>(Ln + r  * W_ + c0);
    const float  tm  = Ln[rm * W_ + cm];
    const float  um  = Ln[r  * W_ + cm];

    float4 q;
    q.x = 0.25f * ((tm + t01.x) + (um + u01.x));
    q.y = 0.5f  * (t01.x + u01.x);
    q.z = 0.25f * ((t01.x + t01.y) + (u01.x + u01.y));
    q.w = 0.5f  * (t01.y + u01.y);

    float* o = out + (size_t)n * (4 * HW_) + (size_t)(2 * r) * (2 * W_) + 2 * c0;
    *reinterpret_cast<float4*>(o) = q;
}

// ---------------------------------------------------------------------------
extern "C" void kernel_launch(void* const* d_in, const int* in_sizes, int n_in,
                              void* d_out, int out_size)
{
    const float* mask_feats = (const float*)d_in[0];
    const float* params     = (const float*)d_in[1];
    const float* inst_loc   = (const float*)d_in[2];
    const float* soi_tab    = (const float*)d_in[3];
    const int*   im_inds    = (const int*)d_in[4];
    const int*   fpn_levels = (const int*)d_in[5];
    float*       out        = (float*)d_out;

    const int n_inst = in_sizes[1] / NPARAMS;   // 128

    dim3 grid1(H_ / 4, (n_inst + GI - 1) / GI);       // 32 x 32 = 1024 blocks
    mask_head_kernel<<<grid1, 192>>>(mask_feats, params, inst_loc, soi_tab,
                                     im_inds, fpn_levels, out, n_inst);

    dim3 grid2(H_ / 16, n_inst);                      // 8 x 128 = 1024 blocks
    dim3 blk2(96, 4);
    upsample_boundary_kernel<<<grid2, blk2>>>(out);
}